// round 3
// baseline (speedup 1.0000x reference)
#include <cuda_runtime.h>
#include <cuda_bf16.h>
#include <cstdint>

// B=32, P=64, D=34, L=1048576
// inputs: preds [B, L] f32, gts [B, P, D, 3] f32   output: [B] f32
// out[b] = sum_{valid} |preds[b, idx] - val| / #persons-with-any-valid-dim

#define RB   32
#define RP   64
#define RD   34
#define RL   1048576
#define NPD  (RP * RD)            // 2176 entries per batch
#define CPB  4                    // CTAs per batch
#define EPC  (NPD / CPB)          // 544 entries per CTA
#define PPC  (RP / CPB)           // 16 persons per CTA
#define NTHREADS 256
#define PER_THREAD ((EPC + NTHREADS - 1) / NTHREADS)   // 3 (threads <32 do 3, rest 2)

// Zero-initialized device scratch for cross-CTA reduction. Last-arriving CTA
// reads-and-resets (atomicExch) so every graph replay starts from zero.
__device__ float        g_sum[RB];
__device__ float        g_np[RB];
__device__ unsigned int g_cnt[RB];

__global__ __launch_bounds__(NTHREADS, 2)
void regl1_kernel(const float* __restrict__ preds,
                  const float* __restrict__ gts,
                  float* __restrict__ out)
{
    const int b    = blockIdx.x >> 2;      // batch
    const int c    = blockIdx.x & 3;       // chunk within batch
    const int tid  = threadIdx.x;
    const int base = c * EPC;              // first entry index for this CTA

    __shared__ float s_any[PPC];           // per-person any-valid flag (local persons)
    __shared__ float s_wsum[NTHREADS / 32];

    if (tid < PPC) s_any[tid] = 0.0f;
    __syncthreads();

    const float* __restrict__ g  = gts   + (size_t)b * NPD * 3;
    const float* __restrict__ pr = preds + (size_t)b * RL;

    // Batch all independent loads (maximize MLP), then consume.
    float val[PER_THREAD], flg[PER_THREAD];
    int   idx[PER_THREAD];

    #pragma unroll
    for (int j = 0; j < PER_THREAD; ++j) {
        const int k = tid + j * NTHREADS;      // entry offset within chunk
        if (k < EPC) {
            const int i = base + k;
            val[j] = g[i * 3 + 0];
            idx[j] = (int)g[i * 3 + 1];
            flg[j] = g[i * 3 + 2];
        } else {
            val[j] = 0.0f; idx[j] = 0; flg[j] = -1.0f;
        }
    }

    float gat[PER_THREAD];
    #pragma unroll
    for (int j = 0; j < PER_THREAD; ++j)
        gat[j] = __ldg(pr + (flg[j] > 0.0f ? idx[j] : 0));

    float sum = 0.0f;
    #pragma unroll
    for (int j = 0; j < PER_THREAD; ++j) {
        const int k = tid + j * NTHREADS;
        if (k < EPC && flg[j] > 0.0f) {
            const int i = base + k;
            sum += fabsf(gat[j] - val[j]);
            s_any[i / RD - c * PPC] = 1.0f;    // benign race: all store 1.0f
        }
    }

    // intra-warp reduction
    #pragma unroll
    for (int off = 16; off > 0; off >>= 1)
        sum += __shfl_down_sync(0xFFFFFFFFu, sum, off);

    const int warp = tid >> 5;
    const int lane = tid & 31;
    if (lane == 0) s_wsum[warp] = sum;
    __syncthreads();

    if (warp == 0) {
        float tot = (lane < (NTHREADS / 32)) ? s_wsum[lane] : 0.0f;
        #pragma unroll
        for (int off = 16; off > 0; off >>= 1)
            tot += __shfl_down_sync(0xFFFFFFFFu, tot, off);

        float np = (lane < PPC) ? s_any[lane] : 0.0f;
        #pragma unroll
        for (int off = 16; off > 0; off >>= 1)
            np += __shfl_down_sync(0xFFFFFFFFu, np, off);

        if (lane == 0) {
            atomicAdd(&g_sum[b], tot);
            atomicAdd(&g_np[b],  np);
            __threadfence();
            const unsigned ticket = atomicAdd(&g_cnt[b], 1u);
            if (ticket == CPB - 1) {
                // all partials are in L2 (each add precedes its ticket)
                const float s = atomicExch(&g_sum[b], 0.0f);
                const float n = atomicExch(&g_np[b],  0.0f);
                out[b] = s / n;               // reference guarantees n >= 1
                g_cnt[b] = 0u;                // ready for next replay
            }
        }
    }
}

extern "C" void kernel_launch(void* const* d_in, const int* in_sizes, int n_in,
                              void* d_out, int out_size)
{
    const float* preds = (const float*)d_in[0];
    const float* gts   = (const float*)d_in[1];
    float* out         = (float*)d_out;
    regl1_kernel<<<RB * CPB, NTHREADS>>>(preds, gts, out);
}

// round 4
// speedup vs baseline: 1.3478x; 1.3478x over previous
#include <cuda_runtime.h>
#include <cuda_bf16.h>
#include <cstdint>

// B=32, P=64, D=34, L=1048576
// inputs: preds [B, L] f32, gts [B, P, D, 3] f32   output: [B] f32
// out[b] = sum_{valid} |preds[b, idx] - val| / #persons-with-any-valid-dim

#define RB   32
#define RP   64
#define RD   34
#define RL   1048576
#define NPD  (RP * RD)            // 2176 entries per batch
#define NTHREADS 1024
#define NWARPS  (NTHREADS / 32)   // 32
#define PER_THREAD ((NPD + NTHREADS - 1) / NTHREADS)  // 3 (tid<128 do 3rd)

__global__ __launch_bounds__(NTHREADS, 1)
void regl1_kernel(const float* __restrict__ preds,
                  const float* __restrict__ gts,
                  float* __restrict__ out)
{
    const int b   = blockIdx.x;
    const int tid = threadIdx.x;

    __shared__ float s_any[RP];        // per-person any-valid flag
    __shared__ float s_wsum[NWARPS];

    if (tid < RP) s_any[tid] = 0.0f;
    __syncthreads();

    const float* __restrict__ g  = gts   + (size_t)b * NPD * 3;
    const float* __restrict__ pr = preds + (size_t)b * RL;

    // Batch all independent gts loads first (maximize MLP).
    float val[PER_THREAD], flg[PER_THREAD];
    unsigned idx[PER_THREAD];

    #pragma unroll
    for (int j = 0; j < PER_THREAD; ++j) {
        const int i = tid + j * NTHREADS;
        if (i < NPD) {
            val[j] = g[i * 3 + 0];
            idx[j] = (unsigned)(int)g[i * 3 + 1];
            flg[j] = g[i * 3 + 2];
        } else {
            val[j] = 0.0f; idx[j] = 0u; flg[j] = -1.0f;
        }
    }

    // Gather unconditionally (idx is always in-range per problem setup; clamp
    // is a 1-op safety net, and keeps the address independent of flg).
    float gat[PER_THREAD];
    #pragma unroll
    for (int j = 0; j < PER_THREAD; ++j)
        gat[j] = __ldg(pr + (idx[j] < RL ? idx[j] : RL - 1u));

    float sum = 0.0f;
    #pragma unroll
    for (int j = 0; j < PER_THREAD; ++j) {
        const int i = tid + j * NTHREADS;
        if (i < NPD && flg[j] > 0.0f) {
            sum += fabsf(gat[j] - val[j]);
            s_any[i / RD] = 1.0f;      // benign race: all writers store 1.0f
        }
    }

    // intra-warp reduction
    #pragma unroll
    for (int off = 16; off > 0; off >>= 1)
        sum += __shfl_down_sync(0xFFFFFFFFu, sum, off);

    const int warp = tid >> 5;
    const int lane = tid & 31;
    if (lane == 0) s_wsum[warp] = sum;
    __syncthreads();

    if (warp == 0) {
        float tot = s_wsum[lane];                       // NWARPS == 32
        #pragma unroll
        for (int off = 16; off > 0; off >>= 1)
            tot += __shfl_down_sync(0xFFFFFFFFu, tot, off);

        float np = s_any[lane] + s_any[lane + 32];      // RP == 64
        #pragma unroll
        for (int off = 16; off > 0; off >>= 1)
            np += __shfl_down_sync(0xFFFFFFFFu, np, off);

        if (lane == 0)
            out[b] = tot / np;        // reference guarantees np >= 1
    }
}

extern "C" void kernel_launch(void* const* d_in, const int* in_sizes, int n_in,
                              void* d_out, int out_size)
{
    const float* preds = (const float*)d_in[0];
    const float* gts   = (const float*)d_in[1];
    float* out         = (float*)d_out;
    regl1_kernel<<<RB, NTHREADS>>>(preds, gts, out);
}